// round 3
// baseline (speedup 1.0000x reference)
#include <cuda_runtime.h>
#include <cuda_bf16.h>

// ---------------- problem constants ----------------
#define BB 2
#define SS 2048
#define DD 2048
#define HH 16
#define NOPE 128
#define ROPE 64
#define VDIM 128
#define QKD 192           // NOPE + ROPE
#define KV_RANK 512
#define KV_A (KV_RANK + ROPE)   // 576
#define KV_PROJ (HH * (NOPE + VDIM)) // 4096
#define EPSV 1e-6f
#define ATT_SCALE 0.07216878364870323f  // 192^-0.5

// ---------------- scratch (static device globals; no allocation) ----------------
__device__ float g_qraw  [(size_t)BB * SS * HH * QKD];       // [B,S,H*192]
__device__ float g_kvall [(size_t)BB * SS * KV_A];           // [B,S,576]
__device__ float g_kvn   [(size_t)BB * SS * KV_RANK];        // [B,S,512]
__device__ float g_kvproj[(size_t)BB * SS * KV_PROJ];        // [B,S,4096]
__device__ float g_Q     [(size_t)BB * HH * SS * QKD];       // [B,H,S,192]
__device__ float g_K     [(size_t)BB * HH * SS * QKD];       // [B,H,S,192]
__device__ float g_Vt    [(size_t)BB * HH * VDIM * SS];      // [B,H,128,S]
__device__ float g_scores[(size_t)BB * HH * SS * SS];        // [B,H,S,S]  (537 MB)
__device__ float g_attn  [(size_t)BB * HH * SS * VDIM];      // [B,H,S,128]
__device__ float g_attn2 [(size_t)BB * SS * HH * VDIM];      // [B,S,H*128]

// ---------------- generic batched GEMM: C = alpha * A @ B^T ----------------
// A: [M,K] row-major (lda), B: [N,K] row-major (ldb), C: [M,N] row-major (ldc)
// Requirements (satisfied by all call sites): K % 16 == 0, lda/ldb % 4 == 0,
// base pointers 16B aligned.
#define BM 128
#define BN 128
#define BKK 16
#define APAD 132   // row pitch (floats); keeps 16B alignment, reduces store conflicts

__global__ __launch_bounds__(256) void gemm_bt(
    const float* __restrict__ A, const float* __restrict__ Bm, float* __restrict__ C,
    int M, int N, int K, int lda, int ldb, int ldc,
    long long sA, long long sB, long long sC, float alpha)
{
    __shared__ float As[BKK][APAD];
    __shared__ float Bs[BKK][APAD];

    const int z = blockIdx.z;
    A  += z * sA;
    Bm += z * sB;
    C  += z * sC;

    const int tid = threadIdx.x;
    const int tx = tid & 15;
    const int ty = tid >> 4;
    const int bm = blockIdx.y * BM;
    const int bn = blockIdx.x * BN;

    // packed f32x2 accumulators: acc2[i][j] holds C cols (tx*8+2j, tx*8+2j+1), row ty*8+i
    unsigned long long acc2[8][4];
#pragma unroll
    for (int i = 0; i < 8; i++)
#pragma unroll
        for (int j = 0; j < 4; j++) acc2[i][j] = 0ULL;

    for (int k0 = 0; k0 < K; k0 += BKK) {
#pragma unroll
        for (int i = 0; i < 2; i++) {
            int v  = tid + i * 256;          // 0..511 (512 float4 per tile)
            int r  = v >> 2;                 // tile row 0..127
            int cg = (v & 3) << 2;           // k-col group {0,4,8,12}
            int gm = bm + r;
            float4 fa = make_float4(0.f, 0.f, 0.f, 0.f);
            if (gm < M) fa = *(const float4*)(A + (long long)gm * lda + (k0 + cg));
            As[cg + 0][r] = fa.x; As[cg + 1][r] = fa.y;
            As[cg + 2][r] = fa.z; As[cg + 3][r] = fa.w;
            int gn = bn + r;
            float4 fb = make_float4(0.f, 0.f, 0.f, 0.f);
            if (gn < N) fb = *(const float4*)(Bm + (long long)gn * ldb + (k0 + cg));
            Bs[cg + 0][r] = fb.x; Bs[cg + 1][r] = fb.y;
            Bs[cg + 2][r] = fb.z; Bs[cg + 3][r] = fb.w;
        }
        __syncthreads();

#pragma unroll
        for (int k = 0; k < BKK; k++) {
            float4 a0 = *(const float4*)&As[k][ty * 8];
            float4 a1 = *(const float4*)&As[k][ty * 8 + 4];
            const unsigned long long* bp = (const unsigned long long*)&Bs[k][tx * 8];
            unsigned long long rb0 = bp[0], rb1 = bp[1], rb2 = bp[2], rb3 = bp[3];
            float ra[8] = {a0.x, a0.y, a0.z, a0.w, a1.x, a1.y, a1.z, a1.w};
#pragma unroll
            for (int i = 0; i < 8; i++) {
                unsigned long long ad;
                asm("mov.b64 %0, {%1, %1};" : "=l"(ad) : "r"(__float_as_uint(ra[i])));
                asm("fma.rn.f32x2 %0, %1, %2, %0;" : "+l"(acc2[i][0]) : "l"(ad), "l"(rb0));
                asm("fma.rn.f32x2 %0, %1, %2, %0;" : "+l"(acc2[i][1]) : "l"(ad), "l"(rb1));
                asm("fma.rn.f32x2 %0, %1, %2, %0;" : "+l"(acc2[i][2]) : "l"(ad), "l"(rb2));
                asm("fma.rn.f32x2 %0, %1, %2, %0;" : "+l"(acc2[i][3]) : "l"(ad), "l"(rb3));
            }
        }
        __syncthreads();
    }

#pragma unroll
    for (int i = 0; i < 8; i++) {
        int gm = bm + ty * 8 + i;
        if (gm >= M) continue;
        float* crow = C + (long long)gm * ldc;
#pragma unroll
        for (int j = 0; j < 4; j++) {
            float2 p = *(float2*)&acc2[i][j];
            int gn = bn + tx * 8 + 2 * j;
            if (gn < N)     crow[gn]     = alpha * p.x;
            if (gn + 1 < N) crow[gn + 1] = alpha * p.y;
        }
    }
}

// ---------------- rmsnorm over KV_RANK (first 512 of kv_all rows) ----------------
__global__ void rmsnorm_kernel(const float* __restrict__ kv_all,
                               const float* __restrict__ w,
                               float* __restrict__ out)
{
    const int row = blockIdx.x;                      // B*S rows
    const float* x = kv_all + (long long)row * KV_A;
    __shared__ float red[256];
    float ss = 0.f;
    for (int i = threadIdx.x; i < KV_RANK; i += 256) { float v = x[i]; ss += v * v; }
    red[threadIdx.x] = ss; __syncthreads();
    for (int st = 128; st > 0; st >>= 1) {
        if (threadIdx.x < st) red[threadIdx.x] += red[threadIdx.x + st];
        __syncthreads();
    }
    float scale = rsqrtf(red[0] / (float)KV_RANK + EPSV);
    float* o = out + (long long)row * KV_RANK;
    for (int i = threadIdx.x; i < KV_RANK; i += 256) o[i] = x[i] * scale * w[i];
}

// ---------------- RoPE + layout prep: build Q [B,H,S,192], K [B,H,S,192], Vt [B,H,128,S] --
__global__ void prepare_kernel(const float* __restrict__ qraw,
                               const float* __restrict__ kvall,
                               const float* __restrict__ kvproj,
                               const float* __restrict__ cosb,
                               const float* __restrict__ sinb,
                               float* __restrict__ Q, float* __restrict__ Kq,
                               float* __restrict__ Vt)
{
    const int bs = blockIdx.x;         // 0..B*S-1
    const int b = bs / SS, s = bs % SS;
    const float* cs = cosb + (long long)s * ROPE;
    const float* sn = sinb + (long long)s * ROPE;

    __shared__ float kpe[ROPE];
    if (threadIdx.x < ROPE) {
        int j = threadIdx.x;
        const float* kp = kvall + (long long)bs * KV_A + KV_RANK;
        float x  = kp[j];
        float xr = (j < 32) ? -kp[j + 32] : kp[j - 32];
        kpe[j] = x * cs[j] + xr * sn[j];
    }
    __syncthreads();

    const float* qrow = qraw + (long long)bs * (HH * QKD);
    const float* prow = kvproj + (long long)bs * KV_PROJ;

    for (int idx = threadIdx.x; idx < HH * QKD; idx += blockDim.x) {
        int h = idx / QKD, d = idx % QKD;
        long long off = (((long long)(b * HH + h)) * SS + s) * QKD + d;
        float qv;
        if (d < NOPE) {
            qv = qrow[h * QKD + d];
        } else {
            int j = d - NOPE;
            float x  = qrow[h * QKD + NOPE + j];
            float xr = (j < 32) ? -qrow[h * QKD + NOPE + j + 32]
                                :  qrow[h * QKD + NOPE + j - 32];
            qv = x * cs[j] + xr * sn[j];
        }
        Q[off] = qv;
        float kv = (d < NOPE) ? prow[h * (NOPE + VDIM) + d] : kpe[d - NOPE];
        Kq[off] = kv;
    }
    for (int idx = threadIdx.x; idx < HH * VDIM; idx += blockDim.x) {
        int h = idx / VDIM, d = idx % VDIM;
        Vt[(((long long)(b * HH + h)) * VDIM + d) * SS + s] =
            prow[h * (NOPE + VDIM) + NOPE + d];
    }
}

// ---------------- row softmax over S, with attention scale folded in ----------------
__global__ void softmax_kernel(float* __restrict__ scores)
{
    const long long row = blockIdx.x;            // B*H*S rows of length S
    float* x = scores + row * (long long)SS;
    const int tid = threadIdx.x;                 // 256 threads, 8 elems each
    float v[8];
    float m = -3.4e38f;
#pragma unroll
    for (int i = 0; i < 8; i++) { v[i] = x[tid + i * 256] * ATT_SCALE; m = fmaxf(m, v[i]); }
    __shared__ float red[256];
    red[tid] = m; __syncthreads();
    for (int st = 128; st > 0; st >>= 1) {
        if (tid < st) red[tid] = fmaxf(red[tid], red[tid + st]);
        __syncthreads();
    }
    m = red[0]; __syncthreads();
    float ssum = 0.f;
#pragma unroll
    for (int i = 0; i < 8; i++) { v[i] = expf(v[i] - m); ssum += v[i]; }
    red[tid] = ssum; __syncthreads();
    for (int st = 128; st > 0; st >>= 1) {
        if (tid < st) red[tid] += red[tid + st];
        __syncthreads();
    }
    float inv = 1.0f / red[0];
#pragma unroll
    for (int i = 0; i < 8; i++) x[tid + i * 256] = v[i] * inv;
}

// ---------------- regroup [B,H,S,128] -> [B,S,H*128] ----------------
__global__ void regroup_kernel(const float* __restrict__ attn, float* __restrict__ out)
{
    long long idx = (long long)blockIdx.x * 256 + threadIdx.x;
    const long long total = (long long)BB * HH * SS * VDIM;
    if (idx >= total) return;
    int d = (int)(idx % VDIM);
    long long t = idx / VDIM;
    int s = (int)(t % SS); t /= SS;
    int h = (int)(t % HH);
    int b = (int)(t / HH);
    out[(((long long)b * SS + s) * (HH * VDIM)) + h * VDIM + d] = attn[idx];
}

// ---------------- launch ----------------
extern "C" void kernel_launch(void* const* d_in, const int* in_sizes, int n_in,
                              void* d_out, int out_size)
{
    const float* x    = (const float*)d_in[0];   // [B,S,D]
    const float* cosb = (const float*)d_in[1];   // [S,64]
    const float* sinb = (const float*)d_in[2];   // [S,64]
    const float* wq   = (const float*)d_in[3];   // [3072,2048]
    const float* wkva = (const float*)d_in[4];   // [576,2048]
    const float* kvw  = (const float*)d_in[5];   // [512]
    const float* wkvb = (const float*)d_in[6];   // [4096,512]
    const float* wo   = (const float*)d_in[7];   // [2048,2048]
    float* out = (float*)d_out;                  // [B,S,D]

    float *qraw, *kvall, *kvn, *kvproj, *Q, *Kq, *Vt, *scores, *attn, *attn2;
    cudaGetSymbolAddress((void**)&qraw,   g_qraw);
    cudaGetSymbolAddress((void**)&kvall,  g_kvall);
    cudaGetSymbolAddress((void**)&kvn,    g_kvn);
    cudaGetSymbolAddress((void**)&kvproj, g_kvproj);
    cudaGetSymbolAddress((void**)&Q,      g_Q);
    cudaGetSymbolAddress((void**)&Kq,     g_K);
    cudaGetSymbolAddress((void**)&Vt,     g_Vt);
    cudaGetSymbolAddress((void**)&scores, g_scores);
    cudaGetSymbolAddress((void**)&attn,   g_attn);
    cudaGetSymbolAddress((void**)&attn2,  g_attn2);

    const int M = BB * SS;                       // 4096

    // 1) q_raw = X @ wq^T            [4096,3072] K=2048
    gemm_bt<<<dim3((HH * QKD + BN - 1) / BN, (M + BM - 1) / BM, 1), 256>>>(
        x, wq, qraw, M, HH * QKD, DD, DD, DD, HH * QKD, 0, 0, 0, 1.f);

    // 2) kv_all = X @ wkv_a^T        [4096,576] K=2048
    gemm_bt<<<dim3((KV_A + BN - 1) / BN, (M + BM - 1) / BM, 1), 256>>>(
        x, wkva, kvall, M, KV_A, DD, DD, DD, KV_A, 0, 0, 0, 1.f);

    // 3) rmsnorm
    rmsnorm_kernel<<<M, 256>>>(kvall, kvw, kvn);

    // 4) kv_proj = kvn @ wkv_b^T     [4096,4096] K=512
    gemm_bt<<<dim3(KV_PROJ / BN, (M + BM - 1) / BM, 1), 256>>>(
        kvn, wkvb, kvproj, M, KV_PROJ, KV_RANK, KV_RANK, KV_RANK, KV_PROJ, 0, 0, 0, 1.f);

    // 5) RoPE + layout
    prepare_kernel<<<M, 256>>>(qraw, kvall, kvproj, cosb, sinb, Q, Kq, Vt);

    // 6) scores = Q @ K^T per (b,h)  [2048,2048] K=192, batch=32
    gemm_bt<<<dim3(SS / BN, SS / BM, BB * HH), 256>>>(
        Q, Kq, scores, SS, SS, QKD, QKD, QKD, SS,
        (long long)SS * QKD, (long long)SS * QKD, (long long)SS * SS, 1.f);

    // 7) softmax rows (scale folded)
    softmax_kernel<<<BB * HH * SS, 256>>>(scores);

    // 8) attn = P @ Vt^T per (b,h)   [2048,128] K=2048, batch=32
    gemm_bt<<<dim3(1, SS / BM, BB * HH), 256>>>(
        scores, Vt, attn, SS, VDIM, SS, SS, SS, VDIM,
        (long long)SS * SS, (long long)VDIM * SS, (long long)SS * VDIM, 1.f);

    // 9) regroup to [B,S,H*128]
    {
        long long total = (long long)BB * HH * SS * VDIM;
        regroup_kernel<<<(unsigned)((total + 255) / 256), 256>>>(attn, attn2);
    }

    // 10) out = attn2 @ wo^T         [4096,2048] K=2048
    gemm_bt<<<dim3(DD / BN, (M + BM - 1) / BM, 1), 256>>>(
        attn2, wo, out, M, DD, HH * VDIM, HH * VDIM, HH * VDIM, DD, 0, 0, 0, 1.f);
}

// round 6
// speedup vs baseline: 1.7047x; 1.7047x over previous
#include <cuda_runtime.h>
#include <cuda_bf16.h>
#include <cstdint>

// ---------------- problem constants ----------------
#define BB 2
#define SS 2048
#define DD 2048
#define HH 16
#define NOPE 128
#define ROPE 64
#define VDIM 128
#define QKD 192           // NOPE + ROPE
#define KV_RANK 512
#define KV_A (KV_RANK + ROPE)   // 576
#define KV_PROJ (HH * (NOPE + VDIM)) // 4096
#define EPSV 1e-6f
#define ATT_SCALE 0.07216878364870323f  // 192^-0.5

// ---------------- scratch (static device globals; no allocation) ----------------
__device__ __align__(16) float g_qraw  [(size_t)BB * SS * HH * QKD];
__device__ __align__(16) float g_kvall [(size_t)BB * SS * KV_A];
__device__ __align__(16) float g_kvn   [(size_t)BB * SS * KV_RANK];
__device__ __align__(16) float g_kvproj[(size_t)BB * SS * KV_PROJ];
__device__ __align__(16) float g_Q     [(size_t)BB * HH * SS * QKD];
__device__ __align__(16) float g_K     [(size_t)BB * HH * SS * QKD];
__device__ __align__(16) float g_Vt    [(size_t)BB * HH * VDIM * SS];
__device__ __align__(16) float g_scores[(size_t)BB * HH * SS * SS];   // 537 MB
__device__ __align__(16) float g_attn  [(size_t)BB * HH * SS * VDIM];
__device__ __align__(16) float g_attn2 [(size_t)BB * SS * HH * VDIM];

// ================= bf16x3 GEMM via mma.sync (compute_103-safe) =================
// C = alpha * A @ B^T.  A:[M,K] row-major, B:[N,K] row-major, C:[M,N] row-major.
// Constraints met by all call sites: K % 32 == 0, M % 128 == 0, N even,
// lda/ldb % 4 == 0, 16B-aligned base pointers.
//
// SMEM (dynamic, 36864 B): Ahi[128][36] | Alo | Bhi | Blo  (bf16, pitch 36 = pad 4)
#define GP 36                 // smem pitch in bf16 elems (72 bytes, 8B-aligned rows)
#define MAT_BYTES (128 * GP * 2)   // 9216
#define GEMM_SMEM (4 * MAT_BYTES)  // 36864

#define MMA16816(d, a, b) \
    asm volatile("mma.sync.aligned.m16n8k16.row.col.f32.bf16.bf16.f32 " \
                 "{%0,%1,%2,%3}, {%4,%5,%6,%7}, {%8,%9}, {%0,%1,%2,%3};" \
                 : "+f"((d)[0]), "+f"((d)[1]), "+f"((d)[2]), "+f"((d)[3]) \
                 : "r"((a)[0]), "r"((a)[1]), "r"((a)[2]), "r"((a)[3]), \
                   "r"((b)[0]), "r"((b)[1]))

__device__ __forceinline__ unsigned pack_hi(float x, float y,
                                            unsigned& lo_out) {
    __nv_bfloat16 hx = __float2bfloat16_rn(x);
    __nv_bfloat16 hy = __float2bfloat16_rn(y);
    __nv_bfloat16 lx = __float2bfloat16_rn(x - __bfloat162float(hx));
    __nv_bfloat16 ly = __float2bfloat16_rn(y - __bfloat162float(hy));
    lo_out = ((unsigned)__bfloat16_as_ushort(ly) << 16) | __bfloat16_as_ushort(lx);
    return ((unsigned)__bfloat16_as_ushort(hy) << 16) | __bfloat16_as_ushort(hx);
}

__global__ __launch_bounds__(256) void gemm_mma(
    const float* __restrict__ A, const float* __restrict__ Bm, float* __restrict__ C,
    int M, int N, int K, int lda, int ldb, int ldc,
    long long sA, long long sB, long long sC, float alpha)
{
    extern __shared__ char sm[];
    char* sAhi = sm;
    char* sAlo = sm + MAT_BYTES;
    char* sBhi = sm + 2 * MAT_BYTES;
    char* sBlo = sm + 3 * MAT_BYTES;

    const int z = blockIdx.z;
    A  += z * sA;
    Bm += z * sB;
    C  += z * sC;

    const int tid  = threadIdx.x;
    const int wid  = tid >> 5;
    const int lane = tid & 31;
    const int g    = lane >> 2;      // 0..7
    const int tig  = lane & 3;       // 0..3
    const int wm   = wid >> 2;       // 0..1 -> m offset wm*64
    const int wn   = wid & 3;        // 0..3 -> n offset wn*32
    const int bm = blockIdx.y * 128;
    const int bn = blockIdx.x * 128;

    float acc[4][4][4];
#pragma unroll
    for (int i = 0; i < 4; i++)
#pragma unroll
        for (int j = 0; j < 4; j++)
#pragma unroll
            for (int q = 0; q < 4; q++) acc[i][j][q] = 0.f;

    const int nc = K >> 5;           // chunks of 32 fp32
    float4 ra[4], rb[4];

    // ---- prefetch chunk 0 ----
    {
        const int k0 = 0;
#pragma unroll
        for (int it = 0; it < 4; it++) {
            int u = tid + (it << 8);         // 0..1023
            int r = u >> 3, q = u & 7;
            ra[it] = *(const float4*)(A + (long long)(bm + r) * lda + k0 + (q << 2));
            int gn = bn + r;
            rb[it] = (gn < N)
                   ? *(const float4*)(Bm + (long long)gn * ldb + k0 + (q << 2))
                   : make_float4(0.f, 0.f, 0.f, 0.f);
        }
    }

    for (int c = 0; c < nc; c++) {
        // ---- convert + STS ----
#pragma unroll
        for (int it = 0; it < 4; it++) {
            int u = tid + (it << 8);
            int r = u >> 3, q = u & 7;
            unsigned off = (unsigned)r * (GP * 2) + (unsigned)(q << 3);
            unsigned lo0, lo1, hi0, hi1;
            hi0 = pack_hi(ra[it].x, ra[it].y, lo0);
            hi1 = pack_hi(ra[it].z, ra[it].w, lo1);
            *(uint2*)(sAhi + off) = make_uint2(hi0, hi1);
            *(uint2*)(sAlo + off) = make_uint2(lo0, lo1);
            hi0 = pack_hi(rb[it].x, rb[it].y, lo0);
            hi1 = pack_hi(rb[it].z, rb[it].w, lo1);
            *(uint2*)(sBhi + off) = make_uint2(hi0, hi1);
            *(uint2*)(sBlo + off) = make_uint2(lo0, lo1);
        }
        __syncthreads();

        // ---- prefetch next chunk ----
        if (c + 1 < nc) {
            const int k0 = (c + 1) << 5;
#pragma unroll
            for (int it = 0; it < 4; it++) {
                int u = tid + (it << 8);
                int r = u >> 3, q = u & 7;
                ra[it] = *(const float4*)(A + (long long)(bm + r) * lda + k0 + (q << 2));
                int gn = bn + r;
                rb[it] = (gn < N)
                       ? *(const float4*)(Bm + (long long)gn * ldb + k0 + (q << 2))
                       : make_float4(0.f, 0.f, 0.f, 0.f);
            }
        }

        // ---- compute: 2 k16 steps ----
#pragma unroll
        for (int kk = 0; kk < 2; kk++) {
            const unsigned kbyte = (unsigned)((kk * 16 + 2 * tig) * 2);
            unsigned bh[4][2], bl[4][2];
#pragma unroll
            for (int nf = 0; nf < 4; nf++) {
                unsigned nrow = (unsigned)(wn * 32 + nf * 8 + g);
                const char* bp = sBhi + nrow * (GP * 2) + kbyte;
                bh[nf][0] = *(const unsigned*)bp;
                bh[nf][1] = *(const unsigned*)(bp + 16);
                const char* bq = sBlo + nrow * (GP * 2) + kbyte;
                bl[nf][0] = *(const unsigned*)bq;
                bl[nf][1] = *(const unsigned*)(bq + 16);
            }
#pragma unroll
            for (int mf = 0; mf < 4; mf++) {
                unsigned mrow = (unsigned)(wm * 64 + mf * 16 + g);
                const char* ap = sAhi + mrow * (GP * 2) + kbyte;
                unsigned ah[4], al[4];
                ah[0] = *(const unsigned*)ap;
                ah[1] = *(const unsigned*)(ap + 8 * GP * 2);
                ah[2] = *(const unsigned*)(ap + 16);
                ah[3] = *(const unsigned*)(ap + 8 * GP * 2 + 16);
                const char* aq = sAlo + mrow * (GP * 2) + kbyte;
                al[0] = *(const unsigned*)aq;
                al[1] = *(const unsigned*)(aq + 8 * GP * 2);
                al[2] = *(const unsigned*)(aq + 16);
                al[3] = *(const unsigned*)(aq + 8 * GP * 2 + 16);
#pragma unroll
                for (int nf = 0; nf < 4; nf++) {
                    MMA16816(acc[mf][nf], ah, bh[nf]);
                    MMA16816(acc[mf][nf], ah, bl[nf]);
                    MMA16816(acc[mf][nf], al, bh[nf]);
                }
            }
        }
        __syncthreads();
    }

    // ---- epilogue ----
#pragma unroll
    for (int mf = 0; mf < 4; mf++) {
#pragma unroll
        for (int nf = 0; nf < 4; nf++) {
            int row = bm + wm * 64 + mf * 16 + g;
            int col = bn + wn * 32 + nf * 8 + 2 * tig;
            if (col < N) {   // N even -> col+1 < N too
                float* p0 = C + (long long)row * ldc + col;
                p0[0] = alpha * acc[mf][nf][0];
                p0[1] = alpha * acc[mf][nf][1];
                float* p1 = p0 + (long long)8 * ldc;
                p1[0] = alpha * acc[mf][nf][2];
                p1[1] = alpha * acc[mf][nf][3];
            }
        }
    }
}

// ---------------- rmsnorm over KV_RANK ----------------
__global__ void rmsnorm_kernel(const float* __restrict__ kv_all,
                               const float* __restrict__ w,
                               float* __restrict__ out)
{
    const int row = blockIdx.x;
    const float* x = kv_all + (long long)row * KV_A;
    __shared__ float red[256];
    float ss = 0.f;
    for (int i = threadIdx.x; i < KV_RANK; i += 256) { float v = x[i]; ss += v * v; }
    red[threadIdx.x] = ss; __syncthreads();
    for (int st = 128; st > 0; st >>= 1) {
        if (threadIdx.x < st) red[threadIdx.x] += red[threadIdx.x + st];
        __syncthreads();
    }
    float scale = rsqrtf(red[0] / (float)KV_RANK + EPSV);
    float* o = out + (long long)row * KV_RANK;
    for (int i = threadIdx.x; i < KV_RANK; i += 256) o[i] = x[i] * scale * w[i];
}

// ---------------- RoPE + layout prep ----------------
__global__ void prepare_kernel(const float* __restrict__ qraw,
                               const float* __restrict__ kvall,
                               const float* __restrict__ kvproj,
                               const float* __restrict__ cosb,
                               const float* __restrict__ sinb,
                               float* __restrict__ Q, float* __restrict__ Kq,
                               float* __restrict__ Vt)
{
    const int bs = blockIdx.x;
    const int b = bs / SS, s = bs % SS;
    const float* cs = cosb + (long long)s * ROPE;
    const float* sn = sinb + (long long)s * ROPE;

    __shared__ float kpe[ROPE];
    if (threadIdx.x < ROPE) {
        int j = threadIdx.x;
        const float* kp = kvall + (long long)bs * KV_A + KV_RANK;
        float x  = kp[j];
        float xr = (j < 32) ? -kp[j + 32] : kp[j - 32];
        kpe[j] = x * cs[j] + xr * sn[j];
    }
    __syncthreads();

    const float* qrow = qraw + (long long)bs * (HH * QKD);
    const float* prow = kvproj + (long long)bs * KV_PROJ;

    for (int idx = threadIdx.x; idx < HH * QKD; idx += blockDim.x) {
        int h = idx / QKD, d = idx % QKD;
        long long off = (((long long)(b * HH + h)) * SS + s) * QKD + d;
        float qv;
        if (d < NOPE) {
            qv = qrow[h * QKD + d];
        } else {
            int j = d - NOPE;
            float x  = qrow[h * QKD + NOPE + j];
            float xr = (j < 32) ? -qrow[h * QKD + NOPE + j + 32]
                                :  qrow[h * QKD + NOPE + j - 32];
            qv = x * cs[j] + xr * sn[j];
        }
        Q[off] = qv;
        float kv = (d < NOPE) ? prow[h * (NOPE + VDIM) + d] : kpe[d - NOPE];
        Kq[off] = kv;
    }
    for (int idx = threadIdx.x; idx < HH * VDIM; idx += blockDim.x) {
        int h = idx / VDIM, d = idx % VDIM;
        Vt[(((long long)(b * HH + h)) * VDIM + d) * SS + s] =
            prow[h * (NOPE + VDIM) + NOPE + d];
    }
}

// ---------------- row softmax over S ----------------
__global__ void softmax_kernel(float* __restrict__ scores)
{
    const long long row = blockIdx.x;
    float* x = scores + row * (long long)SS;
    const int tid = threadIdx.x;
    float v[8];
    float m = -3.4e38f;
#pragma unroll
    for (int i = 0; i < 8; i++) { v[i] = x[tid + i * 256] * ATT_SCALE; m = fmaxf(m, v[i]); }
    __shared__ float red[256];
    red[tid] = m; __syncthreads();
    for (int st = 128; st > 0; st >>= 1) {
        if (tid < st) red[tid] = fmaxf(red[tid], red[tid + st]);
        __syncthreads();
    }
    m = red[0]; __syncthreads();
    float ssum = 0.f;
#pragma unroll
    for (int i = 0; i < 8; i++) { v[i] = expf(v[i] - m); ssum += v[i]; }
    red[tid] = ssum; __syncthreads();
    for (int st = 128; st > 0; st >>= 1) {
        if (tid < st) red[tid] += red[tid + st];
        __syncthreads();
    }
    float inv = 1.0f / red[0];
#pragma unroll
    for (int i = 0; i < 8; i++) x[tid + i * 256] = v[i] * inv;
}

// ---------------- regroup [B,H,S,128] -> [B,S,H*128] ----------------
__global__ void regroup_kernel(const float* __restrict__ attn, float* __restrict__ out)
{
    long long idx = (long long)blockIdx.x * 256 + threadIdx.x;
    const long long total = (long long)BB * HH * SS * VDIM;
    if (idx >= total) return;
    int d = (int)(idx % VDIM);
    long long t = idx / VDIM;
    int s = (int)(t % SS); t /= SS;
    int h = (int)(t % HH);
    int b = (int)(t / HH);
    out[(((long long)b * SS + s) * (HH * VDIM)) + h * VDIM + d] = attn[idx];
}

// ---------------- launch ----------------
extern "C" void kernel_launch(void* const* d_in, const int* in_sizes, int n_in,
                              void* d_out, int out_size)
{
    const float* x    = (const float*)d_in[0];
    const float* cosb = (const float*)d_in[1];
    const float* sinb = (const float*)d_in[2];
    const float* wq   = (const float*)d_in[3];
    const float* wkva = (const float*)d_in[4];
    const float* kvw  = (const float*)d_in[5];
    const float* wkvb = (const float*)d_in[6];
    const float* wo   = (const float*)d_in[7];
    float* out = (float*)d_out;

    float *qraw, *kvall, *kvn, *kvproj, *Q, *Kq, *Vt, *scores, *attn, *attn2;
    cudaGetSymbolAddress((void**)&qraw,   g_qraw);
    cudaGetSymbolAddress((void**)&kvall,  g_kvall);
    cudaGetSymbolAddress((void**)&kvn,    g_kvn);
    cudaGetSymbolAddress((void**)&kvproj, g_kvproj);
    cudaGetSymbolAddress((void**)&Q,      g_Q);
    cudaGetSymbolAddress((void**)&Kq,     g_K);
    cudaGetSymbolAddress((void**)&Vt,     g_Vt);
    cudaGetSymbolAddress((void**)&scores, g_scores);
    cudaGetSymbolAddress((void**)&attn,   g_attn);
    cudaGetSymbolAddress((void**)&attn2,  g_attn2);

    const int M = BB * SS;   // 4096

    // 1) q_raw = X @ wq^T        [4096,3072] K=2048
    gemm_mma<<<dim3(3072 / 128, M / 128, 1), 256, GEMM_SMEM>>>(
        x, wq, qraw, M, HH * QKD, DD, DD, DD, HH * QKD, 0, 0, 0, 1.f);

    // 2) kv_all = X @ wkv_a^T    [4096,576] K=2048
    gemm_mma<<<dim3((KV_A + 127) / 128, M / 128, 1), 256, GEMM_SMEM>>>(
        x, wkva, kvall, M, KV_A, DD, DD, DD, KV_A, 0, 0, 0, 1.f);

    // 3) rmsnorm
    rmsnorm_kernel<<<M, 256>>>(kvall, kvw, kvn);

    // 4) kv_proj = kvn @ wkv_b^T [4096,4096] K=512
    gemm_mma<<<dim3(KV_PROJ / 128, M / 128, 1), 256, GEMM_SMEM>>>(
        kvn, wkvb, kvproj, M, KV_PROJ, KV_RANK, KV_RANK, KV_RANK, KV_PROJ, 0, 0, 0, 1.f);

    // 5) RoPE + layout
    prepare_kernel<<<M, 256>>>(qraw, kvall, kvproj, cosb, sinb, Q, Kq, Vt);

    // 6) scores = Q @ K^T per (b,h)  [2048,2048] K=192, batch=32
    gemm_mma<<<dim3(SS / 128, SS / 128, BB * HH), 256, GEMM_SMEM>>>(
        Q, Kq, scores, SS, SS, QKD, QKD, QKD, SS,
        (long long)SS * QKD, (long long)SS * QKD, (long long)SS * SS, 1.f);

    // 7) softmax rows
    softmax_kernel<<<BB * HH * SS, 256>>>(scores);

    // 8) attn = P @ Vt^T per (b,h)   [2048,128] K=2048, batch=32
    gemm_mma<<<dim3(1, SS / 128, BB * HH), 256, GEMM_SMEM>>>(
        scores, Vt, attn, SS, VDIM, SS, SS, SS, VDIM,
        (long long)SS * SS, (long long)VDIM * SS, (long long)SS * VDIM, 1.f);

    // 9) regroup
    {
        long long total = (long long)BB * HH * SS * VDIM;
        regroup_kernel<<<(unsigned)((total + 255) / 256), 256>>>(attn, attn2);
    }

    // 10) out = attn2 @ wo^T     [4096,2048] K=2048
    gemm_mma<<<dim3(DD / 128, M / 128, 1), 256, GEMM_SMEM>>>(
        attn2, wo, out, M, DD, HH * VDIM, HH * VDIM, HH * VDIM, DD, 0, 0, 0, 1.f);
}

// round 7
// speedup vs baseline: 2.3191x; 1.3604x over previous
#include <cuda_runtime.h>
#include <cuda_bf16.h>
#include <cstdint>

// ---------------- problem constants ----------------
#define BB 2
#define SS 2048
#define DD 2048
#define HH 16
#define NOPE 128
#define ROPE 64
#define VDIM 128
#define QKD 192           // NOPE + ROPE
#define KV_RANK 512
#define KV_A (KV_RANK + ROPE)   // 576
#define KV_PROJ (HH * (NOPE + VDIM)) // 4096
#define EPSV 1e-6f
#define ATT_SCALE 0.07216878364870323f  // 192^-0.5

// ---------------- fp32 scratch ----------------
__device__ __align__(16) float g_qraw  [(size_t)BB * SS * HH * QKD];
__device__ __align__(16) float g_kvall [(size_t)BB * SS * KV_A];
__device__ __align__(16) float g_kvproj[(size_t)BB * SS * KV_PROJ];
__device__ __align__(16) float g_scores[(size_t)BB * HH * SS * SS];   // 537 MB
__device__ __align__(16) float g_attn  [(size_t)BB * HH * SS * VDIM];

// ---------------- bf16 hi/lo scratch ----------------
__device__ __align__(16) __nv_bfloat16 g_xh   [(size_t)BB * SS * DD];
__device__ __align__(16) __nv_bfloat16 g_xl   [(size_t)BB * SS * DD];
__device__ __align__(16) __nv_bfloat16 g_wqh  [(size_t)(HH * QKD) * DD];
__device__ __align__(16) __nv_bfloat16 g_wql  [(size_t)(HH * QKD) * DD];
__device__ __align__(16) __nv_bfloat16 g_wkvah[(size_t)KV_A * DD];
__device__ __align__(16) __nv_bfloat16 g_wkval[(size_t)KV_A * DD];
__device__ __align__(16) __nv_bfloat16 g_wkvbh[(size_t)KV_PROJ * KV_RANK];
__device__ __align__(16) __nv_bfloat16 g_wkvbl[(size_t)KV_PROJ * KV_RANK];
__device__ __align__(16) __nv_bfloat16 g_woh  [(size_t)DD * DD];
__device__ __align__(16) __nv_bfloat16 g_wol  [(size_t)DD * DD];
__device__ __align__(16) __nv_bfloat16 g_kvnh [(size_t)BB * SS * KV_RANK];
__device__ __align__(16) __nv_bfloat16 g_kvnl [(size_t)BB * SS * KV_RANK];
__device__ __align__(16) __nv_bfloat16 g_Qh   [(size_t)BB * HH * SS * QKD];
__device__ __align__(16) __nv_bfloat16 g_Ql   [(size_t)BB * HH * SS * QKD];
__device__ __align__(16) __nv_bfloat16 g_Kh   [(size_t)BB * HH * SS * QKD];
__device__ __align__(16) __nv_bfloat16 g_Kl   [(size_t)BB * HH * SS * QKD];
__device__ __align__(16) __nv_bfloat16 g_Vth  [(size_t)BB * HH * VDIM * SS];
__device__ __align__(16) __nv_bfloat16 g_Vtl  [(size_t)BB * HH * VDIM * SS];
__device__ __align__(16) __nv_bfloat16 g_Ph   [(size_t)BB * HH * SS * SS];  // 256 MB
__device__ __align__(16) __nv_bfloat16 g_Pl   [(size_t)BB * HH * SS * SS];  // 256 MB
__device__ __align__(16) __nv_bfloat16 g_a2h  [(size_t)BB * SS * HH * VDIM];
__device__ __align__(16) __nv_bfloat16 g_a2l  [(size_t)BB * SS * HH * VDIM];

// ---------------- helpers ----------------
__device__ __forceinline__ uint32_t smem_u32(const void* p) {
    uint32_t a;
    asm("{ .reg .u64 t; cvta.to.shared.u64 t, %1; cvt.u32.u64 %0, t; }" : "=r"(a) : "l"(p));
    return a;
}
__device__ __forceinline__ void split2(float x, __nv_bfloat16& h, __nv_bfloat16& l) {
    h = __float2bfloat16_rn(x);
    l = __float2bfloat16_rn(x - __bfloat162float(h));
}
__device__ __forceinline__ void cp16(uint32_t d, const void* s) {
    asm volatile("cp.async.cg.shared.global [%0], [%1], 16;" :: "r"(d), "l"(s));
}
__device__ __forceinline__ void cp16z(uint32_t d, const void* s, unsigned bytes) {
    asm volatile("cp.async.cg.shared.global [%0], [%1], 16, %2;" :: "r"(d), "l"(s), "r"(bytes));
}

#define MMA16816(d, a, b) \
    asm volatile("mma.sync.aligned.m16n8k16.row.col.f32.bf16.bf16.f32 " \
                 "{%0,%1,%2,%3}, {%4,%5,%6,%7}, {%8,%9}, {%0,%1,%2,%3};" \
                 : "+f"((d)[0]), "+f"((d)[1]), "+f"((d)[2]), "+f"((d)[3]) \
                 : "r"((a)[0]), "r"((a)[1]), "r"((a)[2]), "r"((a)[3]), \
                   "r"((b)[0]), "r"((b)[1]))

// ================= bf16x3 GEMM, pre-split inputs, cp.async + ldmatrix ==========
// C = alpha * (Ah+Al) @ (Bh+Bl)^T (3-term). A:[M,K] bf16 row-major ×2, B:[N,K] ×2.
// CTA tile 128x128, BK=32, 2-stage cp.async pipeline, 256 threads, 2 CTAs/SM.
// SMEM per stage: 4 matrices × 128 rows × 80 B = 40960 B. Total 81920 B.
#define MATP 80
#define MOFF 10240u
#define STAGEB 40960u
#define GEMM3_SMEM (2 * 40960)

__device__ __forceinline__ void g3_issue(
    uint32_t sb,
    const __nv_bfloat16* __restrict__ Ah, const __nv_bfloat16* __restrict__ Al,
    const __nv_bfloat16* __restrict__ Bh, const __nv_bfloat16* __restrict__ Bl,
    int bm, int bn, int N, int lda, int ldb, int k0, int tid)
{
#pragma unroll
    for (int half = 0; half < 2; half++) {
        int r  = (tid >> 2) + half * 64;
        int sg = tid & 3;
        uint32_t d = sb + (uint32_t)(r * MATP + sg * 16);
        long long ko = (long long)k0 + sg * 8;
        cp16(d,        Ah + (long long)(bm + r) * lda + ko);
        cp16(d + MOFF, Al + (long long)(bm + r) * lda + ko);
        int gn = bn + r;
        unsigned bytes = (gn < N) ? 16u : 0u;
        int gr = (gn < N) ? gn : 0;
        cp16z(d + 2 * MOFF, Bh + (long long)gr * ldb + ko, bytes);
        cp16z(d + 3 * MOFF, Bl + (long long)gr * ldb + ko, bytes);
    }
    asm volatile("cp.async.commit_group;" ::: "memory");
}

__global__ __launch_bounds__(256, 2) void gemm3(
    const __nv_bfloat16* __restrict__ Ah, const __nv_bfloat16* __restrict__ Al,
    const __nv_bfloat16* __restrict__ Bh, const __nv_bfloat16* __restrict__ Bl,
    float* __restrict__ C,
    int M, int N, int K, int lda, int ldb, int ldc,
    long long sA, long long sB, long long sC, float alpha)
{
    extern __shared__ char sm[];
    const int z = blockIdx.z;
    Ah += z * sA; Al += z * sA; Bh += z * sB; Bl += z * sB; C += z * sC;

    const int tid  = threadIdx.x;
    const int lane = tid & 31;
    const int wid  = tid >> 5;
    const int g    = lane >> 2;
    const int tig  = lane & 3;
    const int wm   = wid >> 2;       // 0..1
    const int wn   = wid & 3;        // 0..3
    const int bm = blockIdx.y * 128;
    const int bn = blockIdx.x * 128;
    const uint32_t smb = smem_u32(sm);

    float acc[4][4][4];
#pragma unroll
    for (int i = 0; i < 4; i++)
#pragma unroll
        for (int j = 0; j < 4; j++)
#pragma unroll
            for (int q = 0; q < 4; q++) acc[i][j][q] = 0.f;

    const int nc = K >> 5;

    g3_issue(smb, Ah, Al, Bh, Bl, bm, bn, N, lda, ldb, 0, tid);

    // ldmatrix lane bases
    const uint32_t aAddr = smb +
        (uint32_t)((wm * 64 + (lane & 15)) * MATP + ((lane >> 4) << 4));
    const int l15 = lane & 15;
    const uint32_t bAddr = smb + 2u * MOFF +
        (uint32_t)((wn * 32 + (l15 & 7)) * MATP + ((l15 >> 3) << 4));

    for (int c = 0; c < nc; c++) {
        const uint32_t sboff = (uint32_t)(c & 1) * STAGEB;
        if (c + 1 < nc) {
            g3_issue(smb + (uint32_t)((c + 1) & 1) * STAGEB,
                     Ah, Al, Bh, Bl, bm, bn, N, lda, ldb, (c + 1) << 5, tid);
            asm volatile("cp.async.wait_group 1;" ::: "memory");
        } else {
            asm volatile("cp.async.wait_group 0;" ::: "memory");
        }
        __syncthreads();

#pragma unroll
        for (int kk = 0; kk < 2; kk++) {
            unsigned bh[4][2], blr[4][2];
#pragma unroll
            for (int nf = 0; nf < 4; nf++) {
                uint32_t ad = bAddr + sboff + (uint32_t)(nf * (8 * MATP) + kk * 32);
                asm volatile("ldmatrix.sync.aligned.m8n8.x2.shared.b16 {%0,%1}, [%2];"
                             : "=r"(bh[nf][0]), "=r"(bh[nf][1]) : "r"(ad));
                asm volatile("ldmatrix.sync.aligned.m8n8.x2.shared.b16 {%0,%1}, [%2];"
                             : "=r"(blr[nf][0]), "=r"(blr[nf][1]) : "r"(ad + MOFF));
            }
#pragma unroll
            for (int mf = 0; mf < 4; mf++) {
                uint32_t ad = aAddr + sboff + (uint32_t)(mf * (16 * MATP) + kk * 32);
                unsigned ah[4], al[4];
                asm volatile("ldmatrix.sync.aligned.m8n8.x4.shared.b16 {%0,%1,%2,%3}, [%4];"
                             : "=r"(ah[0]), "=r"(ah[1]), "=r"(ah[2]), "=r"(ah[3]) : "r"(ad));
                asm volatile("ldmatrix.sync.aligned.m8n8.x4.shared.b16 {%0,%1,%2,%3}, [%4];"
                             : "=r"(al[0]), "=r"(al[1]), "=r"(al[2]), "=r"(al[3]) : "r"(ad + MOFF));
#pragma unroll
                for (int nf = 0; nf < 4; nf++) {
                    MMA16816(acc[mf][nf], ah, bh[nf]);
                    MMA16816(acc[mf][nf], ah, blr[nf]);
                    MMA16816(acc[mf][nf], al, bh[nf]);
                }
            }
        }
        __syncthreads();
    }

    // ---- epilogue ----
#pragma unroll
    for (int mf = 0; mf < 4; mf++) {
#pragma unroll
        for (int nf = 0; nf < 4; nf++) {
            int row = bm + wm * 64 + mf * 16 + g;
            int col = bn + wn * 32 + nf * 8 + 2 * tig;
            if (col < N) {
                float* p0 = C + (long long)row * ldc + col;
                p0[0] = alpha * acc[mf][nf][0];
                p0[1] = alpha * acc[mf][nf][1];
                float* p1 = p0 + (long long)8 * ldc;
                p1[0] = alpha * acc[mf][nf][2];
                p1[1] = alpha * acc[mf][nf][3];
            }
        }
    }
}

// ---------------- fp32 -> bf16 hi/lo converter (vectorized, grid-stride) -------
__global__ void convert_kernel(const float* __restrict__ in,
                               __nv_bfloat16* __restrict__ hp,
                               __nv_bfloat16* __restrict__ lp, long long n4)
{
    for (long long i = (long long)blockIdx.x * 256 + threadIdx.x; i < n4;
         i += (long long)gridDim.x * 256) {
        float4 v = ((const float4*)in)[i];
        __nv_bfloat16 h0, h1, h2, h3, l0, l1, l2, l3;
        split2(v.x, h0, l0); split2(v.y, h1, l1);
        split2(v.z, h2, l2); split2(v.w, h3, l3);
        uint2 hh, ll;
        hh.x = ((unsigned)__bfloat16_as_ushort(h1) << 16) | __bfloat16_as_ushort(h0);
        hh.y = ((unsigned)__bfloat16_as_ushort(h3) << 16) | __bfloat16_as_ushort(h2);
        ll.x = ((unsigned)__bfloat16_as_ushort(l1) << 16) | __bfloat16_as_ushort(l0);
        ll.y = ((unsigned)__bfloat16_as_ushort(l3) << 16) | __bfloat16_as_ushort(l2);
        ((uint2*)hp)[i] = hh;
        ((uint2*)lp)[i] = ll;
    }
}

// ---------------- rmsnorm over KV_RANK -> bf16 hi/lo ----------------
__global__ void rmsnorm_kernel(const float* __restrict__ kv_all,
                               const float* __restrict__ w,
                               __nv_bfloat16* __restrict__ oh,
                               __nv_bfloat16* __restrict__ ol)
{
    const int row = blockIdx.x;
    const float* x = kv_all + (long long)row * KV_A;
    __shared__ float red[256];
    float ss = 0.f;
    for (int i = threadIdx.x; i < KV_RANK; i += 256) { float v = x[i]; ss += v * v; }
    red[threadIdx.x] = ss; __syncthreads();
    for (int st = 128; st > 0; st >>= 1) {
        if (threadIdx.x < st) red[threadIdx.x] += red[threadIdx.x + st];
        __syncthreads();
    }
    float scale = rsqrtf(red[0] / (float)KV_RANK + EPSV);
    for (int i = threadIdx.x; i < KV_RANK; i += 256) {
        float v = x[i] * scale * w[i];
        __nv_bfloat16 h, l; split2(v, h, l);
        oh[(long long)row * KV_RANK + i] = h;
        ol[(long long)row * KV_RANK + i] = l;
    }
}

// ---------------- RoPE + layout prep -> bf16 hi/lo ----------------
__global__ void prepare_kernel(const float* __restrict__ qraw,
                               const float* __restrict__ kvall,
                               const float* __restrict__ kvproj,
                               const float* __restrict__ cosb,
                               const float* __restrict__ sinb,
                               __nv_bfloat16* __restrict__ Qh, __nv_bfloat16* __restrict__ Ql,
                               __nv_bfloat16* __restrict__ Kh, __nv_bfloat16* __restrict__ Kl,
                               __nv_bfloat16* __restrict__ Vth, __nv_bfloat16* __restrict__ Vtl)
{
    const int bs = blockIdx.x;
    const int b = bs / SS, s = bs % SS;
    const float* cs = cosb + (long long)s * ROPE;
    const float* sn = sinb + (long long)s * ROPE;

    __shared__ float kpe[ROPE];
    if (threadIdx.x < ROPE) {
        int j = threadIdx.x;
        const float* kp = kvall + (long long)bs * KV_A + KV_RANK;
        float x  = kp[j];
        float xr = (j < 32) ? -kp[j + 32] : kp[j - 32];
        kpe[j] = x * cs[j] + xr * sn[j];
    }
    __syncthreads();

    const float* qrow = qraw + (long long)bs * (HH * QKD);
    const float* prow = kvproj + (long long)bs * KV_PROJ;

    for (int idx = threadIdx.x; idx < HH * QKD; idx += blockDim.x) {
        int h = idx / QKD, d = idx % QKD;
        long long off = (((long long)(b * HH + h)) * SS + s) * QKD + d;
        float qv;
        if (d < NOPE) {
            qv = qrow[h * QKD + d];
        } else {
            int j = d - NOPE;
            float x  = qrow[h * QKD + NOPE + j];
            float xr = (j < 32) ? -qrow[h * QKD + NOPE + j + 32]
                                :  qrow[h * QKD + NOPE + j - 32];
            qv = x * cs[j] + xr * sn[j];
        }
        __nv_bfloat16 hh, ll;
        split2(qv, hh, ll); Qh[off] = hh; Ql[off] = ll;
        float kv = (d < NOPE) ? prow[h * (NOPE + VDIM) + d] : kpe[d - NOPE];
        split2(kv, hh, ll); Kh[off] = hh; Kl[off] = ll;
    }
    for (int idx = threadIdx.x; idx < HH * VDIM; idx += blockDim.x) {
        int h = idx / VDIM, d = idx % VDIM;
        long long off = (((long long)(b * HH + h)) * VDIM + d) * SS + s;
        float v = prow[h * (NOPE + VDIM) + NOPE + d];
        __nv_bfloat16 hh, ll; split2(v, hh, ll);
        Vth[off] = hh; Vtl[off] = ll;
    }
}

// ---------------- row softmax over S (fp32 in) -> bf16 hi/lo P ----------------
__global__ void softmax_kernel(const float* __restrict__ scores,
                               __nv_bfloat16* __restrict__ Ph,
                               __nv_bfloat16* __restrict__ Pl)
{
    const long long row = blockIdx.x;
    const float* x = scores + row * (long long)SS;
    const int tid = threadIdx.x;
    float v[8];
    float m = -3.4e38f;
#pragma unroll
    for (int i = 0; i < 8; i++) { v[i] = x[tid + i * 256] * ATT_SCALE; m = fmaxf(m, v[i]); }
    __shared__ float red[256];
    red[tid] = m; __syncthreads();
    for (int st = 128; st > 0; st >>= 1) {
        if (tid < st) red[tid] = fmaxf(red[tid], red[tid + st]);
        __syncthreads();
    }
    m = red[0]; __syncthreads();
    float ssum = 0.f;
#pragma unroll
    for (int i = 0; i < 8; i++) { v[i] = expf(v[i] - m); ssum += v[i]; }
    red[tid] = ssum; __syncthreads();
    for (int st = 128; st > 0; st >>= 1) {
        if (tid < st) red[tid] += red[tid + st];
        __syncthreads();
    }
    float inv = 1.0f / red[0];
#pragma unroll
    for (int i = 0; i < 8; i++) {
        float p = v[i] * inv;
        __nv_bfloat16 h, l; split2(p, h, l);
        long long o = row * (long long)SS + tid + i * 256;
        Ph[o] = h; Pl[o] = l;
    }
}

// ---------------- regroup [B,H,S,128] -> [B,S,H*128] bf16 hi/lo ----------------
__global__ void regroup_kernel(const float* __restrict__ attn,
                               __nv_bfloat16* __restrict__ oh,
                               __nv_bfloat16* __restrict__ ol)
{
    long long idx = (long long)blockIdx.x * 256 + threadIdx.x;
    const long long total = (long long)BB * HH * SS * VDIM;
    if (idx >= total) return;
    int d = (int)(idx % VDIM);
    long long t = idx / VDIM;
    int s = (int)(t % SS); t /= SS;
    int h = (int)(t % HH);
    int b = (int)(t / HH);
    long long o = (((long long)b * SS + s) * (HH * VDIM)) + h * VDIM + d;
    __nv_bfloat16 hh, ll; split2(attn[idx], hh, ll);
    oh[o] = hh; ol[o] = ll;
}

// ---------------- launch ----------------
extern "C" void kernel_launch(void* const* d_in, const int* in_sizes, int n_in,
                              void* d_out, int out_size)
{
    const float* x    = (const float*)d_in[0];
    const float* cosb = (const float*)d_in[1];
    const float* sinb = (const float*)d_in[2];
    const float* wq   = (const float*)d_in[3];
    const float* wkva = (const float*)d_in[4];
    const float* kvw  = (const float*)d_in[5];
    const float* wkvb = (const float*)d_in[6];
    const float* wo   = (const float*)d_in[7];
    float* out = (float*)d_out;

    cudaFuncSetAttribute(gemm3, cudaFuncAttributeMaxDynamicSharedMemorySize, GEMM3_SMEM);

    float *qraw, *kvall, *kvproj, *scores, *attn;
    cudaGetSymbolAddress((void**)&qraw,   g_qraw);
    cudaGetSymbolAddress((void**)&kvall,  g_kvall);
    cudaGetSymbolAddress((void**)&kvproj, g_kvproj);
    cudaGetSymbolAddress((void**)&scores, g_scores);
    cudaGetSymbolAddress((void**)&attn,   g_attn);

    __nv_bfloat16 *xh, *xl, *wqh, *wql, *wkvah, *wkval, *wkvbh, *wkvbl, *woh, *wol;
    __nv_bfloat16 *kvnh, *kvnl, *Qh, *Ql, *Kh, *Kl, *Vth, *Vtl, *Ph, *Pl, *a2h, *a2l;
    cudaGetSymbolAddress((void**)&xh,    g_xh);    cudaGetSymbolAddress((void**)&xl,    g_xl);
    cudaGetSymbolAddress((void**)&wqh,   g_wqh);   cudaGetSymbolAddress((void**)&wql,   g_wql);
    cudaGetSymbolAddress((void**)&wkvah, g_wkvah); cudaGetSymbolAddress((void**)&wkval, g_wkval);
    cudaGetSymbolAddress((void**)&wkvbh, g_wkvbh); cudaGetSymbolAddress((void**)&wkvbl, g_wkvbl);
    cudaGetSymbolAddress((void**)&woh,   g_woh);   cudaGetSymbolAddress((void**)&wol,   g_wol);
    cudaGetSymbolAddress((void**)&kvnh,  g_kvnh);  cudaGetSymbolAddress((void**)&kvnl,  g_kvnl);
    cudaGetSymbolAddress((void**)&Qh,    g_Qh);    cudaGetSymbolAddress((void**)&Ql,    g_Ql);
    cudaGetSymbolAddress((void**)&Kh,    g_Kh);    cudaGetSymbolAddress((void**)&Kl,    g_Kl);
    cudaGetSymbolAddress((void**)&Vth,   g_Vth);   cudaGetSymbolAddress((void**)&Vtl,   g_Vtl);
    cudaGetSymbolAddress((void**)&Ph,    g_Ph);    cudaGetSymbolAddress((void**)&Pl,    g_Pl);
    cudaGetSymbolAddress((void**)&a2h,   g_a2h);   cudaGetSymbolAddress((void**)&a2l,   g_a2l);

    const int M = BB * SS;   // 4096

    // 0) pre-split inputs/weights to bf16 hi/lo
    convert_kernel<<<1024, 256>>>(x,    xh,    xl,    (long long)BB * SS * DD / 4);
    convert_kernel<<<1024, 256>>>(wq,   wqh,   wql,   (long long)(HH * QKD) * DD / 4);
    convert_kernel<<<1024, 256>>>(wkva, wkvah, wkval, (long long)KV_A * DD / 4);
    convert_kernel<<<1024, 256>>>(wkvb, wkvbh, wkvbl, (long long)KV_PROJ * KV_RANK / 4);
    convert_kernel<<<1024, 256>>>(wo,   woh,   wol,   (long long)DD * DD / 4);

    // 1) q_raw = X @ wq^T        [4096,3072] K=2048
    gemm3<<<dim3(3072 / 128, M / 128, 1), 256, GEMM3_SMEM>>>(
        xh, xl, wqh, wql, qraw, M, HH * QKD, DD, DD, DD, HH * QKD, 0, 0, 0, 1.f);

    // 2) kv_all = X @ wkv_a^T    [4096,576] K=2048
    gemm3<<<dim3((KV_A + 127) / 128, M / 128, 1), 256, GEMM3_SMEM>>>(
        xh, xl, wkvah, wkval, kvall, M, KV_A, DD, DD, DD, KV_A, 0, 0, 0, 1.f);

    // 3) rmsnorm -> bf16 hi/lo
    rmsnorm_kernel<<<M, 256>>>(kvall, kvw, kvnh, kvnl);

    // 4) kv_proj = kvn @ wkv_b^T [4096,4096] K=512
    gemm3<<<dim3(KV_PROJ / 128, M / 128, 1), 256, GEMM3_SMEM>>>(
        kvnh, kvnl, wkvbh, wkvbl, kvproj, M, KV_PROJ, KV_RANK,
        KV_RANK, KV_RANK, KV_PROJ, 0, 0, 0, 1.f);

    // 5) RoPE + layout -> bf16 hi/lo Q/K/Vt
    prepare_kernel<<<M, 256>>>(qraw, kvall, kvproj, cosb, sinb, Qh, Ql, Kh, Kl, Vth, Vtl);

    // 6) scores = Q @ K^T per (b,h)  [2048,2048] K=192, batch=32
    gemm3<<<dim3(SS / 128, SS / 128, BB * HH), 256, GEMM3_SMEM>>>(
        Qh, Ql, Kh, Kl, scores, SS, SS, QKD, QKD, QKD, SS,
        (long long)SS * QKD, (long long)SS * QKD, (long long)SS * SS, 1.f);

    // 7) softmax rows -> bf16 hi/lo P
    softmax_kernel<<<BB * HH * SS, 256>>>(scores, Ph, Pl);

    // 8) attn = P @ Vt^T per (b,h)   [2048,128] K=2048, batch=32
    gemm3<<<dim3(1, SS / 128, BB * HH), 256, GEMM3_SMEM>>>(
        Ph, Pl, Vth, Vtl, attn, SS, VDIM, SS, SS, SS, VDIM,
        (long long)SS * SS, (long long)VDIM * SS, (long long)SS * VDIM, 1.f);

    // 9) regroup -> bf16 hi/lo attn2
    {
        long long total = (long long)BB * HH * SS * VDIM;
        regroup_kernel<<<(unsigned)((total + 255) / 256), 256>>>(attn, a2h, a2l);
    }

    // 10) out = attn2 @ wo^T     [4096,2048] K=2048
    gemm3<<<dim3(DD / 128, M / 128, 1), 256, GEMM3_SMEM>>>(
        a2h, a2l, woh, wol, out, M, DD, HH * VDIM,
        HH * VDIM, HH * VDIM, DD, 0, 0, 0, 1.f);
}

// round 9
// speedup vs baseline: 2.5596x; 1.1037x over previous
#include <cuda_runtime.h>
#include <cuda_bf16.h>
#include <cstdint>

// ---------------- problem constants ----------------
#define BB 2
#define SS 2048
#define DD 2048
#define HH 16
#define NOPE 128
#define ROPE 64
#define VDIM 128
#define QKD 192           // NOPE + ROPE
#define KV_RANK 512
#define KV_A (KV_RANK + ROPE)   // 576
#define KV_PROJ (HH * (NOPE + VDIM)) // 4096
#define EPSV 1e-6f
#define ATT_SCALE 0.07216878364870323f  // 192^-0.5

// ---------------- fp32 scratch ----------------
__device__ __align__(16) float g_qraw  [(size_t)BB * SS * HH * QKD];
__device__ __align__(16) float g_kvall [(size_t)BB * SS * KV_A];
__device__ __align__(16) float g_kvproj[(size_t)BB * SS * KV_PROJ];
__device__ __align__(16) float g_scores[(size_t)BB * HH * SS * SS];   // 537 MB
__device__ __align__(16) float g_attn  [(size_t)BB * HH * SS * VDIM];

// ---------------- bf16 hi/lo scratch ----------------
__device__ __align__(16) __nv_bfloat16 g_xh   [(size_t)BB * SS * DD];
__device__ __align__(16) __nv_bfloat16 g_xl   [(size_t)BB * SS * DD];
__device__ __align__(16) __nv_bfloat16 g_wqh  [(size_t)(HH * QKD) * DD];
__device__ __align__(16) __nv_bfloat16 g_wql  [(size_t)(HH * QKD) * DD];
__device__ __align__(16) __nv_bfloat16 g_wkvah[(size_t)KV_A * DD];
__device__ __align__(16) __nv_bfloat16 g_wkval[(size_t)KV_A * DD];
__device__ __align__(16) __nv_bfloat16 g_wkvbh[(size_t)KV_PROJ * KV_RANK];
__device__ __align__(16) __nv_bfloat16 g_wkvbl[(size_t)KV_PROJ * KV_RANK];
__device__ __align__(16) __nv_bfloat16 g_woh  [(size_t)DD * DD];
__device__ __align__(16) __nv_bfloat16 g_wol  [(size_t)DD * DD];
__device__ __align__(16) __nv_bfloat16 g_kvnh [(size_t)BB * SS * KV_RANK];
__device__ __align__(16) __nv_bfloat16 g_kvnl [(size_t)BB * SS * KV_RANK];
__device__ __align__(16) __nv_bfloat16 g_Qh   [(size_t)BB * HH * SS * QKD];
__device__ __align__(16) __nv_bfloat16 g_Ql   [(size_t)BB * HH * SS * QKD];
__device__ __align__(16) __nv_bfloat16 g_Kh   [(size_t)BB * HH * SS * QKD];
__device__ __align__(16) __nv_bfloat16 g_Kl   [(size_t)BB * HH * SS * QKD];
__device__ __align__(16) __nv_bfloat16 g_Vth  [(size_t)BB * HH * VDIM * SS];
__device__ __align__(16) __nv_bfloat16 g_Vtl  [(size_t)BB * HH * VDIM * SS];
__device__ __align__(16) __nv_bfloat16 g_Ph   [(size_t)BB * HH * SS * SS];  // 256 MB
__device__ __align__(16) __nv_bfloat16 g_Pl   [(size_t)BB * HH * SS * SS];  // 256 MB
__device__ __align__(16) __nv_bfloat16 g_a2h  [(size_t)BB * SS * HH * VDIM];
__device__ __align__(16) __nv_bfloat16 g_a2l  [(size_t)BB * SS * HH * VDIM];

// ---------------- helpers ----------------
__device__ __forceinline__ uint32_t smem_u32(const void* p) {
    uint32_t a;
    asm("{ .reg .u64 t; cvta.to.shared.u64 t, %1; cvt.u32.u64 %0, t; }" : "=r"(a) : "l"(p));
    return a;
}
__device__ __forceinline__ void split2(float x, __nv_bfloat16& h, __nv_bfloat16& l) {
    h = __float2bfloat16_rn(x);
    l = __float2bfloat16_rn(x - __bfloat162float(h));
}
__device__ __forceinline__ void cp16(uint32_t d, const void* s) {
    asm volatile("cp.async.cg.shared.global [%0], [%1], 16;" :: "r"(d), "l"(s));
}
__device__ __forceinline__ void cp16z(uint32_t d, const void* s, unsigned bytes) {
    asm volatile("cp.async.cg.shared.global [%0], [%1], 16, %2;" :: "r"(d), "l"(s), "r"(bytes));
}

#define MMA16816(d, a, b) \
    asm volatile("mma.sync.aligned.m16n8k16.row.col.f32.bf16.bf16.f32 " \
                 "{%0,%1,%2,%3}, {%4,%5,%6,%7}, {%8,%9}, {%0,%1,%2,%3};" \
                 : "+f"((d)[0]), "+f"((d)[1]), "+f"((d)[2]), "+f"((d)[3]) \
                 : "r"((a)[0]), "r"((a)[1]), "r"((a)[2]), "r"((a)[3]), \
                   "r"((b)[0]), "r"((b)[1]))

// ================= bf16x3 GEMM: 3-stage cp.async, swizzled 64B rows ============
// C = alpha * (Ah+Al) @ (Bh+Bl)^T (3-term). A:[M,K] bf16 ×2, B:[N,K] bf16 ×2.
// CTA tile 128x128, BK=32, 256 threads, 2 CTAs/SM.
// Row layout: 64B rows (32 bf16). Physical 16B chunk p = c ^ ((r>>1)&3).
//   cp.async stores: lanes 0..3 cover one row's 4 chunks (permuted) -> conflict-free.
//   ldmatrix phases: 8 rows, fixed c -> bank groups (4r + c^((r>>1)&3)) % 8 all
//   distinct -> conflict-free.
// SMEM: 3 stages x 4 mats x 128 rows x 64B = 98304 B.
#define MOFF 8192u
#define STG  32768u
#define GEMM3_SMEM 98304

__device__ __forceinline__ void g3_issue(
    uint32_t sb,
    const __nv_bfloat16* __restrict__ Ah, const __nv_bfloat16* __restrict__ Al,
    const __nv_bfloat16* __restrict__ Bh, const __nv_bfloat16* __restrict__ Bl,
    int bm, int bn, int N, int lda, int ldb, int k0, int tid)
{
#pragma unroll
    for (int half = 0; half < 2; half++) {
        int r  = (tid >> 2) + half * 64;
        int sg = tid & 3;
        int p  = sg ^ ((r >> 1) & 3);
        uint32_t d = sb + (uint32_t)(r * 64 + p * 16);
        long long ko = (long long)k0 + sg * 8;
        cp16(d,        Ah + (long long)(bm + r) * lda + ko);
        cp16(d + MOFF, Al + (long long)(bm + r) * lda + ko);
        int gn = bn + r;
        unsigned bytes = (gn < N) ? 16u : 0u;
        int gr = (gn < N) ? gn : 0;
        cp16z(d + 2 * MOFF, Bh + (long long)gr * ldb + ko, bytes);
        cp16z(d + 3 * MOFF, Bl + (long long)gr * ldb + ko, bytes);
    }
    asm volatile("cp.async.commit_group;" ::: "memory");
}

__global__ __launch_bounds__(256, 2) void gemm3(
    const __nv_bfloat16* __restrict__ Ah, const __nv_bfloat16* __restrict__ Al,
    const __nv_bfloat16* __restrict__ Bh, const __nv_bfloat16* __restrict__ Bl,
    float* __restrict__ C,
    int M, int N, int K, int lda, int ldb, int ldc,
    long long sA, long long sB, long long sC, float alpha)
{
    extern __shared__ char sm[];
    const int z = blockIdx.z;
    Ah += z * sA; Al += z * sA; Bh += z * sB; Bl += z * sB; C += z * sC;

    const int tid  = threadIdx.x;
    const int lane = tid & 31;
    const int wid  = tid >> 5;
    const int g    = lane >> 2;
    const int tig  = lane & 3;
    const int wm   = wid >> 2;       // 0..1
    const int wn   = wid & 3;        // 0..3
    const int bm = blockIdx.y * 128;
    const int bn = blockIdx.x * 128;
    const uint32_t smb = smem_u32(sm);

    float acc[4][4][4];
#pragma unroll
    for (int i = 0; i < 4; i++)
#pragma unroll
        for (int j = 0; j < 4; j++)
#pragma unroll
            for (int q = 0; q < 4; q++) acc[i][j][q] = 0.f;

    const int nc = K >> 5;

    // prologue: stages 0, 1
    g3_issue(smb,       Ah, Al, Bh, Bl, bm, bn, N, lda, ldb, 0,  tid);
    g3_issue(smb + STG, Ah, Al, Bh, Bl, bm, bn, N, lda, ldb, 32, tid);

    // ldmatrix lane constants
    const int l15 = lane & 15;
    const int l7  = lane & 7;
    const uint32_t aSel = (uint32_t)(lane >> 4);          // 0/1: +16B chunk
    const uint32_t bSel = (uint32_t)(l15 >> 3);           // 0/1
    const uint32_t swzA = (uint32_t)((l15 >> 1) & 3);
    const uint32_t swzB = (uint32_t)((l7 >> 1) & 3);
    const uint32_t aBase = smb + (uint32_t)((wm * 64 + l15) * 64);
    const uint32_t bBase = smb + 2u * MOFF + (uint32_t)((wn * 32 + l7) * 64);

    for (int c = 0; c < nc; c++) {
        asm volatile("cp.async.wait_group 1;" ::: "memory");
        __syncthreads();

        // issue stage c+2 into buffer freed by stage c-1 (safe after the barrier)
        if (c + 2 < nc) {
            g3_issue(smb + (uint32_t)((c + 2) % 3) * STG,
                     Ah, Al, Bh, Bl, bm, bn, N, lda, ldb, (c + 2) << 5, tid);
        } else {
            asm volatile("cp.async.commit_group;" ::: "memory");
        }

        const uint32_t so = (uint32_t)(c % 3) * STG;
#pragma unroll
        for (int kk = 0; kk < 2; kk++) {
            const uint32_t cA = (uint32_t)(kk * 2) + aSel;
            const uint32_t cB = (uint32_t)(kk * 2) + bSel;
            unsigned bh[4][2], blr[4][2];
#pragma unroll
            for (int nf = 0; nf < 4; nf++) {
                uint32_t ad = bBase + so + (uint32_t)(nf * 512) + ((cB ^ swzB) << 4);
                asm volatile("ldmatrix.sync.aligned.m8n8.x2.shared.b16 {%0,%1}, [%2];"
                             : "=r"(bh[nf][0]), "=r"(bh[nf][1]) : "r"(ad));
                asm volatile("ldmatrix.sync.aligned.m8n8.x2.shared.b16 {%0,%1}, [%2];"
                             : "=r"(blr[nf][0]), "=r"(blr[nf][1]) : "r"(ad + MOFF));
            }
#pragma unroll
            for (int mf = 0; mf < 4; mf++) {
                uint32_t ad = aBase + so + (uint32_t)(mf * 1024) + ((cA ^ swzA) << 4);
                unsigned ah[4], al[4];
                asm volatile("ldmatrix.sync.aligned.m8n8.x4.shared.b16 {%0,%1,%2,%3}, [%4];"
                             : "=r"(ah[0]), "=r"(ah[1]), "=r"(ah[2]), "=r"(ah[3]) : "r"(ad));
                asm volatile("ldmatrix.sync.aligned.m8n8.x4.shared.b16 {%0,%1,%2,%3}, [%4];"
                             : "=r"(al[0]), "=r"(al[1]), "=r"(al[2]), "=r"(al[3]) : "r"(ad + MOFF));
#pragma unroll
                for (int nf = 0; nf < 4; nf++) {
                    MMA16816(acc[mf][nf], ah, bh[nf]);
                    MMA16816(acc[mf][nf], ah, blr[nf]);
                    MMA16816(acc[mf][nf], al, bh[nf]);
                }
            }
        }
    }

    // ---- epilogue ----
#pragma unroll
    for (int mf = 0; mf < 4; mf++) {
#pragma unroll
        for (int nf = 0; nf < 4; nf++) {
            int row = bm + wm * 64 + mf * 16 + g;
            int col = bn + wn * 32 + nf * 8 + 2 * tig;
            if (col < N) {
                float* p0 = C + (long long)row * ldc + col;
                p0[0] = alpha * acc[mf][nf][0];
                p0[1] = alpha * acc[mf][nf][1];
                float* p1 = p0 + (long long)8 * ldc;
                p1[0] = alpha * acc[mf][nf][2];
                p1[1] = alpha * acc[mf][nf][3];
            }
        }
    }
}

// ---------------- fp32 -> bf16 hi/lo converter (vectorized, grid-stride) -------
__global__ void convert_kernel(const float* __restrict__ in,
                               __nv_bfloat16* __restrict__ hp,
                               __nv_bfloat16* __restrict__ lp, long long n4)
{
    for (long long i = (long long)blockIdx.x * 256 + threadIdx.x; i < n4;
         i += (long long)gridDim.x * 256) {
        float4 v = ((const float4*)in)[i];
        __nv_bfloat16 h0, h1, h2, h3, l0, l1, l2, l3;
        split2(v.x, h0, l0); split2(v.y, h1, l1);
        split2(v.z, h2, l2); split2(v.w, h3, l3);
        uint2 hh, ll;
        hh.x = ((unsigned)__bfloat16_as_ushort(h1) << 16) | __bfloat16_as_ushort(h0);
        hh.y = ((unsigned)__bfloat16_as_ushort(h3) << 16) | __bfloat16_as_ushort(h2);
        ll.x = ((unsigned)__bfloat16_as_ushort(l1) << 16) | __bfloat16_as_ushort(l0);
        ll.y = ((unsigned)__bfloat16_as_ushort(l3) << 16) | __bfloat16_as_ushort(l2);
        ((uint2*)hp)[i] = hh;
        ((uint2*)lp)[i] = ll;
    }
}

// ---------------- rmsnorm over KV_RANK -> bf16 hi/lo ----------------
__global__ void rmsnorm_kernel(const float* __restrict__ kv_all,
                               const float* __restrict__ w,
                               __nv_bfloat16* __restrict__ oh,
                               __nv_bfloat16* __restrict__ ol)
{
    const int row = blockIdx.x;
    const float* x = kv_all + (long long)row * KV_A;
    __shared__ float red[256];
    float ss = 0.f;
    for (int i = threadIdx.x; i < KV_RANK; i += 256) { float v = x[i]; ss += v * v; }
    red[threadIdx.x] = ss; __syncthreads();
    for (int st = 128; st > 0; st >>= 1) {
        if (threadIdx.x < st) red[threadIdx.x] += red[threadIdx.x + st];
        __syncthreads();
    }
    float scale = rsqrtf(red[0] / (float)KV_RANK + EPSV);
    for (int i = threadIdx.x; i < KV_RANK; i += 256) {
        float v = x[i] * scale * w[i];
        __nv_bfloat16 h, l; split2(v, h, l);
        oh[(long long)row * KV_RANK + i] = h;
        ol[(long long)row * KV_RANK + i] = l;
    }
}

// ---------------- RoPE + layout prep -> bf16 hi/lo ----------------
__global__ void prepare_kernel(const float* __restrict__ qraw,
                               const float* __restrict__ kvall,
                               const float* __restrict__ kvproj,
                               const float* __restrict__ cosb,
                               const float* __restrict__ sinb,
                               __nv_bfloat16* __restrict__ Qh, __nv_bfloat16* __restrict__ Ql,
                               __nv_bfloat16* __restrict__ Kh, __nv_bfloat16* __restrict__ Kl,
                               __nv_bfloat16* __restrict__ Vth, __nv_bfloat16* __restrict__ Vtl)
{
    const int bs = blockIdx.x;
    const int b = bs / SS, s = bs % SS;
    const float* cs = cosb + (long long)s * ROPE;
    const float* sn = sinb + (long long)s * ROPE;

    __shared__ float kpe[ROPE];
    if (threadIdx.x < ROPE) {
        int j = threadIdx.x;
        const float* kp = kvall + (long long)bs * KV_A + KV_RANK;
        float x  = kp[j];
        float xr = (j < 32) ? -kp[j + 32] : kp[j - 32];
        kpe[j] = x * cs[j] + xr * sn[j];
    }
    __syncthreads();

    const float* qrow = qraw + (long long)bs * (HH * QKD);
    const float* prow = kvproj + (long long)bs * KV_PROJ;

    for (int idx = threadIdx.x; idx < HH * QKD; idx += blockDim.x) {
        int h = idx / QKD, d = idx % QKD;
        long long off = (((long long)(b * HH + h)) * SS + s) * QKD + d;
        float qv;
        if (d < NOPE) {
            qv = qrow[h * QKD + d];
        } else {
            int j = d - NOPE;
            float x  = qrow[h * QKD + NOPE + j];
            float xr = (j < 32) ? -qrow[h * QKD + NOPE + j + 32]
                                :  qrow[h * QKD + NOPE + j - 32];
            qv = x * cs[j] + xr * sn[j];
        }
        __nv_bfloat16 hh, ll;
        split2(qv, hh, ll); Qh[off] = hh; Ql[off] = ll;
        float kv = (d < NOPE) ? prow[h * (NOPE + VDIM) + d] : kpe[d - NOPE];
        split2(kv, hh, ll); Kh[off] = hh; Kl[off] = ll;
    }
    for (int idx = threadIdx.x; idx < HH * VDIM; idx += blockDim.x) {
        int h = idx / VDIM, d = idx % VDIM;
        long long off = (((long long)(b * HH + h)) * VDIM + d) * SS + s;
        float v = prow[h * (NOPE + VDIM) + NOPE + d];
        __nv_bfloat16 hh, ll; split2(v, hh, ll);
        Vth[off] = hh; Vtl[off] = ll;
    }
}

// ---------------- row softmax over S (fp32 in) -> bf16 hi/lo P ----------------
__global__ void softmax_kernel(const float* __restrict__ scores,
                               __nv_bfloat16* __restrict__ Ph,
                               __nv_bfloat16* __restrict__ Pl)
{
    const long long row = blockIdx.x;
    const float* x = scores + row * (long long)SS;
    const int tid = threadIdx.x;
    float v[8];
    float m = -3.4e38f;
#pragma unroll
    for (int i = 0; i < 8; i++) { v[i] = x[tid + i * 256] * ATT_SCALE; m = fmaxf(m, v[i]); }
    __shared__ float red[256];
    red[tid] = m; __syncthreads();
    for (int st = 128; st > 0; st >>= 1) {
        if (tid < st) red[tid] = fmaxf(red[tid], red[tid + st]);
        __syncthreads();
    }
    m = red[0]; __syncthreads();
    float ssum = 0.f;
#pragma unroll
    for (int i = 0; i < 8; i++) { v[i] = expf(v[i] - m); ssum += v[i]; }
    red[tid] = ssum; __syncthreads();
    for (int st = 128; st > 0; st >>= 1) {
        if (tid < st) red[tid] += red[tid + st];
        __syncthreads();
    }
    float inv = 1.0f / red[0];
#pragma unroll
    for (int i = 0; i < 8; i++) {
        float p = v[i] * inv;
        __nv_bfloat16 h, l; split2(p, h, l);
        long long o = row * (long long)SS + tid + i * 256;
        Ph[o] = h; Pl[o] = l;
    }
}

// ---------------- regroup [B,H,S,128] -> [B,S,H*128] bf16 hi/lo ----------------
__global__ void regroup_kernel(const float* __restrict__ attn,
                               __nv_bfloat16* __restrict__ oh,
                               __nv_bfloat16* __restrict__ ol)
{
    long long idx = (long long)blockIdx.x * 256 + threadIdx.x;
    const long long total = (long long)BB * HH * SS * VDIM;
    if (idx >= total) return;
    int d = (int)(idx % VDIM);
    long long t = idx / VDIM;
    int s = (int)(t % SS); t /= SS;
    int h = (int)(t % HH);
    int b = (int)(t / HH);
    long long o = (((long long)b * SS + s) * (HH * VDIM)) + h * VDIM + d;
    __nv_bfloat16 hh, ll; split2(attn[idx], hh, ll);
    oh[o] = hh; ol[o] = ll;
}

// ---------------- launch ----------------
extern "C" void kernel_launch(void* const* d_in, const int* in_sizes, int n_in,
                              void* d_out, int out_size)
{
    const float* x    = (const float*)d_in[0];
    const float* cosb = (const float*)d_in[1];
    const float* sinb = (const float*)d_in[2];
    const float* wq   = (const float*)d_in[3];
    const float* wkva = (const float*)d_in[4];
    const float* kvw  = (const float*)d_in[5];
    const float* wkvb = (const float*)d_in[6];
    const float* wo   = (const float*)d_in[7];
    float* out = (float*)d_out;

    cudaFuncSetAttribute(gemm3, cudaFuncAttributeMaxDynamicSharedMemorySize, GEMM3_SMEM);

    float *qraw, *kvall, *kvproj, *scores, *attn;
    cudaGetSymbolAddress((void**)&qraw,   g_qraw);
    cudaGetSymbolAddress((void**)&kvall,  g_kvall);
    cudaGetSymbolAddress((void**)&kvproj, g_kvproj);
    cudaGetSymbolAddress((void**)&scores, g_scores);
    cudaGetSymbolAddress((void**)&attn,   g_attn);

    __nv_bfloat16 *xh, *xl, *wqh, *wql, *wkvah, *wkval, *wkvbh, *wkvbl, *woh, *wol;
    __nv_bfloat16 *kvnh, *kvnl, *Qh, *Ql, *Kh, *Kl, *Vth, *Vtl, *Ph, *Pl, *a2h, *a2l;
    cudaGetSymbolAddress((void**)&xh,    g_xh);    cudaGetSymbolAddress((void**)&xl,    g_xl);
    cudaGetSymbolAddress((void**)&wqh,   g_wqh);   cudaGetSymbolAddress((void**)&wql,   g_wql);
    cudaGetSymbolAddress((void**)&wkvah, g_wkvah); cudaGetSymbolAddress((void**)&wkval, g_wkval);
    cudaGetSymbolAddress((void**)&wkvbh, g_wkvbh); cudaGetSymbolAddress((void**)&wkvbl, g_wkvbl);
    cudaGetSymbolAddress((void**)&woh,   g_woh);   cudaGetSymbolAddress((void**)&wol,   g_wol);
    cudaGetSymbolAddress((void**)&kvnh,  g_kvnh);  cudaGetSymbolAddress((void**)&kvnl,  g_kvnl);
    cudaGetSymbolAddress((void**)&Qh,    g_Qh);    cudaGetSymbolAddress((void**)&Ql,    g_Ql);
    cudaGetSymbolAddress((void**)&Kh,    g_Kh);    cudaGetSymbolAddress((void**)&Kl,    g_Kl);
    cudaGetSymbolAddress((void**)&Vth,   g_Vth);   cudaGetSymbolAddress((void**)&Vtl,   g_Vtl);
    cudaGetSymbolAddress((void**)&Ph,    g_Ph);    cudaGetSymbolAddress((void**)&Pl,    g_Pl);
    cudaGetSymbolAddress((void**)&a2h,   g_a2h);   cudaGetSymbolAddress((void**)&a2l,   g_a2l);

    const int M = BB * SS;   // 4096

    // 0) pre-split inputs/weights to bf16 hi/lo
    convert_kernel<<<1024, 256>>>(x,    xh,    xl,    (long long)BB * SS * DD / 4);
    convert_kernel<<<1024, 256>>>(wq,   wqh,   wql,   (long long)(HH * QKD) * DD / 4);
    convert_kernel<<<1024, 256>>>(wkva, wkvah, wkval, (long long)KV_A * DD / 4);
    convert_kernel<<<1024, 256>>>(wkvb, wkvbh, wkvbl, (long long)KV_PROJ * KV_RANK / 4);
    convert_kernel<<<1024, 256>>>(wo,   woh,   wol,   (long long)DD * DD / 4);

    // 1) q_raw = X @ wq^T        [4096,3072] K=2048
    gemm3<<<dim3(3072 / 128, M / 128, 1), 256, GEMM3_SMEM>>>(
        xh, xl, wqh, wql, qraw, M, HH * QKD, DD, DD, DD, HH * QKD, 0, 0, 0, 1.f);

    // 2) kv_all = X @ wkv_a^T    [4096,576] K=2048
    gemm3<<<dim3((KV_A + 127) / 128, M / 128, 1), 256, GEMM3_SMEM>>>(
        xh, xl, wkvah, wkval, kvall, M, KV_A, DD, DD, DD, KV_A, 0, 0, 0, 1.f);

    // 3) rmsnorm -> bf16 hi/lo
    rmsnorm_kernel<<<M, 256>>>(kvall, kvw, kvnh, kvnl);

    // 4) kv_proj = kvn @ wkv_b^T [4096,4096] K=512
    gemm3<<<dim3(KV_PROJ / 128, M / 128, 1), 256, GEMM3_SMEM>>>(
        kvnh, kvnl, wkvbh, wkvbl, kvproj, M, KV_PROJ, KV_RANK,
        KV_RANK, KV_RANK, KV_PROJ, 0, 0, 0, 1.f);

    // 5) RoPE + layout -> bf16 hi/lo Q/K/Vt
    prepare_kernel<<<M, 256>>>(qraw, kvall, kvproj, cosb, sinb, Qh, Ql, Kh, Kl, Vth, Vtl);

    // 6) scores = Q @ K^T per (b,h)  [2048,2048] K=192, batch=32
    gemm3<<<dim3(SS / 128, SS / 128, BB * HH), 256, GEMM3_SMEM>>>(
        Qh, Ql, Kh, Kl, scores, SS, SS, QKD, QKD, QKD, SS,
        (long long)SS * QKD, (long long)SS * QKD, (long long)SS * SS, 1.f);

    // 7) softmax rows -> bf16 hi/lo P
    softmax_kernel<<<BB * HH * SS, 256>>>(scores, Ph, Pl);

    // 8) attn = P @ Vt^T per (b,h)   [2048,128] K=2048, batch=32
    gemm3<<<dim3(1, SS / 128, BB * HH), 256, GEMM3_SMEM>>>(
        Ph, Pl, Vth, Vtl, attn, SS, VDIM, SS, SS, SS, VDIM,
        (long long)SS * SS, (long long)VDIM * SS, (long long)SS * VDIM, 1.f);

    // 9) regroup -> bf16 hi/lo attn2
    {
        long long total = (long long)BB * HH * SS * VDIM;
        regroup_kernel<<<(unsigned)((total + 255) / 256), 256>>>(attn, a2h, a2l);
    }

    // 10) out = attn2 @ wo^T     [4096,2048] K=2048
    gemm3<<<dim3(DD / 128, M / 128, 1), 256, GEMM3_SMEM>>>(
        a2h, a2l, woh, wol, out, M, DD, HH * VDIM,
        HH * VDIM, HH * VDIM, DD, 0, 0, 0, 1.f);
}